// round 4
// baseline (speedup 1.0000x reference)
#include <cuda_runtime.h>
#include <math.h>

#define BATCH 16
#define HW 65536

// ---- scratch (device globals) ----
__device__ float dS[BATCH*HW];
__device__ float dPmn[BATCH*8*128];   // per-block min partials [b][o][blk]
__device__ float dPmx[BATCH*8*128];
__device__ float dHist[4096];
__device__ float dTotal;
__device__ float dZg[BATCH*64*56*16]; // [b][gh][gw][m]

__device__ __forceinline__ float lrelu(float v){ return v >= 0.f ? v : 0.01f*v; }

// ---- K1: fused box-pool (channel sum) + per-orientation clamped-LBP block min/max ----
// Also zeroes dHist/dTotal for the later k_hist accumulation (disjoint chunks, no race).
__global__ void __launch_bounds__(256) k_pool_minmax(const float* __restrict__ x,
                                                     const float* __restrict__ clo,
                                                     const float* __restrict__ chi){
    __shared__ float xs[20][36];   // sum-of-3-channels, halo 2
    __shared__ float St[18][34];   // pooled S, halo 1
    __shared__ float red[8][16];
    int b  = blockIdx.z;
    int h0 = blockIdx.y*16, w0 = blockIdx.x*32;
    int tx = threadIdx.x, ty = threadIdx.y;
    int tid = ty*32 + tx;
    const float* xb = x + (size_t)b*3*HW;

    if (blockIdx.x == 0 && blockIdx.y == 0){
        dHist[b*256 + tid] = 0.f;
        if (b == 0 && tid == 0) dTotal = 0.f;
    }

    for (int i = tid; i < 720; i += 256){
        int r = i/36, c = i - r*36;
        int h = h0-2+r, w = w0-2+c;
        float v = 0.f;
        if ((unsigned)h < 256u && (unsigned)w < 256u){
            int off = (h<<8) | w;
            v = xb[off] + xb[HW+off] + xb[2*HW+off];
        }
        xs[r][c] = v;
    }
    __syncthreads();

    for (int i = tid; i < 612; i += 256){
        int r = i/34, c = i - r*34;
        int h = h0-1+r, w = w0-1+c;
        float s = 0.f;
        if ((unsigned)h < 256u && (unsigned)w < 256u){
            s = (xs[r  ][c] + xs[r  ][c+1] + xs[r  ][c+2]
               + xs[r+1][c] + xs[r+1][c+1] + xs[r+1][c+2]
               + xs[r+2][c] + xs[r+2][c+1] + xs[r+2][c+2]) / 9.0f;
            if (r >= 1 && r < 17 && c >= 1 && c < 33)
                dS[b*HW + (h<<8) + w] = s;
        }
        St[r][c] = s;
    }
    __syncthreads();

    const int DY[8] = {-1,1,-1,1,-1,1,0,0};
    const int DX[8] = {-1,1,0,0,1,-1,1,-1};
    float lo = clo[0], hi = chi[0];
    float mn[8], mx[8];
    #pragma unroll
    for (int o = 0; o < 8; o++){ mn[o] = 3.4e38f; mx[o] = -3.4e38f; }

    #pragma unroll
    for (int ph = 0; ph < 2; ph++){
        int r = ty + ph*8 + 1, c = tx + 1;
        float ctr = St[r][c];
        #pragma unroll
        for (int o = 0; o < 8; o++){
            float v = fminf(fmaxf(ctr - St[r+DY[o]][c+DX[o]], lo), hi);
            mn[o] = fminf(mn[o], v);
            mx[o] = fmaxf(mx[o], v);
        }
    }
    #pragma unroll
    for (int o = 0; o < 8; o++){
        #pragma unroll
        for (int off = 16; off; off >>= 1){
            mn[o] = fminf(mn[o], __shfl_xor_sync(0xffffffffu, mn[o], off));
            mx[o] = fmaxf(mx[o], __shfl_xor_sync(0xffffffffu, mx[o], off));
        }
    }
    int warp = tid >> 5, lane = tid & 31;
    if (lane == 0){
        #pragma unroll
        for (int o = 0; o < 8; o++){ red[warp][o] = mn[o]; red[warp][8+o] = mx[o]; }
    }
    __syncthreads();
    int blk = blockIdx.y*8 + blockIdx.x;   // 0..127 within batch
    if (tid < 16){
        if (tid < 8){
            float v = red[0][tid];
            #pragma unroll
            for (int w2 = 1; w2 < 8; w2++) v = fminf(v, red[w2][tid]);
            dPmn[(b*8 + tid)*128 + blk] = v;
        } else {
            float v = red[0][tid];
            #pragma unroll
            for (int w2 = 1; w2 < 8; w2++) v = fmaxf(v, red[w2][tid]);
            dPmx[(b*8 + tid - 8)*128 + blk] = v;
        }
    }
}

// ---- K2: product histogram (4 groups per pass) + global total; reduces minmax partials inline ----
__global__ void __launch_bounds__(256) k_hist(const float* __restrict__ clo,
                                              const float* __restrict__ chi){
    __shared__ float St[18][34];
    __shared__ float sh[8][256];     // per-warp: 4 groups x 64 bins
    __shared__ float lv[8][8];
    __shared__ float smn[8], sscale[8];
    __shared__ float rawmn[8], rawmx[8];
    __shared__ float redt[8];
    int b  = blockIdx.z;
    int h0 = blockIdx.y*16, w0 = blockIdx.x*32;
    int tid = threadIdx.x;
    int warp = tid >> 5, lane = tid & 31;
    const float* Sb = dS + b*HW;

    // reduce per-block min/max partials (warp o handles orientation o)
    {
        const float* pmn = &dPmn[(b*8 + warp)*128];
        const float* pmx = &dPmx[(b*8 + warp)*128];
        float mn = fminf(fminf(pmn[lane], pmn[lane+32]), fminf(pmn[lane+64], pmn[lane+96]));
        float mx = fmaxf(fmaxf(pmx[lane], pmx[lane+32]), fmaxf(pmx[lane+64], pmx[lane+96]));
        #pragma unroll
        for (int off = 16; off; off >>= 1){
            mn = fminf(mn, __shfl_xor_sync(0xffffffffu, mn, off));
            mx = fmaxf(mx, __shfl_xor_sync(0xffffffffu, mx, off));
        }
        if (lane == 0){ rawmn[warp] = mn; rawmx[warp] = mx; }
    }

    for (int i = tid; i < 612; i += 256){
        int r = i/34, c = i - r*34;
        int h = h0-1+r, w = w0-1+c;
        St[r][c] = ((unsigned)h < 256u && (unsigned)w < 256u) ? Sb[(h<<8)+w] : 0.f;
    }
    for (int i = tid; i < 2048; i += 256) ((float*)sh)[i] = 0.f;
    __syncthreads();

    if (tid < 64){
        int o = tid >> 3, q = tid & 7;
        float mnv = rawmn[o], mxv = rawmx[o];
        float r = mxv - mnv;
        lv[o][q] = __fadd_rn(mnv, __fmul_rn(r, q*0.125f));
        if (q == 0){ smn[o] = mnv; sscale[o] = (r > 0.f) ? 8.0f/r : 0.f; }
    }
    __syncthreads();

    const int DY[8] = {-1,1,-1,1,-1,1,0,0};
    const int DX[8] = {-1,1,0,0,1,-1,1,-1};
    float lo = clo[0], hic = chi[0];
    int tx = tid & 31, ty = tid >> 5;

    #pragma unroll
    for (int ph = 0; ph < 2; ph++){
        int r = ty + ph*8 + 1, c = tx + 1;
        float ctr = St[r][c];
        float vv[8]; int qq[8]; unsigned tie = 0;
        #pragma unroll
        for (int o = 0; o < 8; o++){
            float v = fminf(fmaxf(ctr - St[r+DY[o]][c+DX[o]], lo), hic);
            float f = (v - smn[o]) * sscale[o];
            int q = (int)f; q = q < 0 ? 0 : (q > 7 ? 7 : q);
            if (q < 7 && v >= lv[o][q+1]) q++;
            if (q < 7 && v >= lv[o][q+1]) q++;
            if (q > 0 && v <  lv[o][q])   q--;
            if (q > 0 && v <  lv[o][q])   q--;
            vv[o] = v; qq[o] = q;
            if (q > 0 && v == lv[o][q]) tie |= 1u << o;
        }
        #pragma unroll
        for (int g = 0; g < 4; g++){
            float prod = vv[2*g] * vv[2*g+1];
            int qi = qq[2*g], qj = qq[2*g+1];
            atomicAdd(&sh[warp][g*64 + qi*8 + qj], prod);
            if (tie & (3u << (2*g))){
                if (tie & (1u << (2*g)))   atomicAdd(&sh[warp][g*64 + (qi-1)*8 + qj], prod);
                if (tie & (1u << (2*g+1))) atomicAdd(&sh[warp][g*64 + qi*8 + (qj-1)], prod);
                if (((tie >> (2*g)) & 3u) == 3u)
                                           atomicAdd(&sh[warp][g*64 + (qi-1)*8 + (qj-1)], prod);
            }
        }
    }
    __syncthreads();

    float s;
    {
        int g = tid >> 6, bin = tid & 63;
        s = sh[0][g*64+bin] + sh[1][g*64+bin] + sh[2][g*64+bin] + sh[3][g*64+bin]
          + sh[4][g*64+bin] + sh[5][g*64+bin] + sh[6][g*64+bin] + sh[7][g*64+bin];
        atomicAdd(&dHist[(b*4+g)*64 + bin], s);
    }
    #pragma unroll
    for (int off = 16; off; off >>= 1) s += __shfl_xor_sync(0xffffffffu, s, off);
    if (lane == 0) redt[warp] = s;
    __syncthreads();
    if (tid == 0){
        float t = 0.f;
        #pragma unroll
        for (int w2 = 0; w2 < 8; w2++) t += redt[w2];
        atomicAdd(&dTotal, t);
    }
}

// ---- K3: fused expand-conv + instance-norm stats + normalized 4->16 conv, one block per batch ----
__global__ void __launch_bounds__(256) k_grid(const float* __restrict__ we,
                                              const float* __restrict__ be,
                                              const float* __restrict__ wc,
                                              const float* __restrict__ bc){
    __shared__ float hist_s[256];
    __shared__ float we_s[168], be_s[56], wc_s[64], bc_s[16];
    __shared__ float sred[8][8];
    __shared__ float mean_s[4], inv_s[4];
    int b = blockIdx.x;
    int tid = threadIdx.x;
    int warp = tid >> 5, lane = tid & 31;

    hist_s[tid] = dHist[b*256 + tid];
    if (tid < 168) we_s[tid] = we[tid];
    if (tid < 56)  be_s[tid] = be[tid];
    if (tid < 64)  wc_s[tid] = wc[tid];
    if (tid < 16)  bc_s[tid] = bc[tid];
    __syncthreads();
    float total = dTotal;

    // pass 1: weighted stats per group
    float s[4] = {0,0,0,0}, sq[4] = {0,0,0,0};
    for (int e = tid; e < 3584; e += 256){
        int p = e / 56, oc = e - p*56;
        int cnt = (((oc+1)*256 + 55)/56) - ((oc*256 + 55)/56);
        float wgt = (float)(cnt*4);
        float base = we_s[oc*3+0]*(float)(p>>3) + we_s[oc*3+1]*(float)(p&7) + be_s[oc];
        float w2 = we_s[oc*3+2];
        #pragma unroll
        for (int g = 0; g < 4; g++){
            float hn = hist_s[g*64+p] / total;
            float y = lrelu(base + w2*hn);
            s[g]  += y*wgt;
            sq[g] += y*y*wgt;
        }
    }
    #pragma unroll
    for (int g = 0; g < 4; g++){
        #pragma unroll
        for (int off = 16; off; off >>= 1){
            s[g]  += __shfl_xor_sync(0xffffffffu, s[g],  off);
            sq[g] += __shfl_xor_sync(0xffffffffu, sq[g], off);
        }
    }
    if (lane == 0){
        #pragma unroll
        for (int g = 0; g < 4; g++){ sred[warp][g] = s[g]; sred[warp][4+g] = sq[g]; }
    }
    __syncthreads();
    if (tid < 4){
        float ts = 0.f, tq = 0.f;
        #pragma unroll
        for (int w2 = 0; w2 < 8; w2++){ ts += sred[w2][tid]; tq += sred[w2][4+tid]; }
        float mean = ts / 65536.f;
        float var  = tq / 65536.f - mean*mean;
        mean_s[tid] = mean;
        inv_s[tid]  = 1.f / sqrtf(fmaxf(var, 0.f) + 1e-5f);
    }
    __syncthreads();

    // pass 2: normalized 4->16 conv, write zgrid
    float m0 = mean_s[0], m1 = mean_s[1], m2 = mean_s[2], m3 = mean_s[3];
    float i0 = inv_s[0],  i1 = inv_s[1],  i2 = inv_s[2],  i3 = inv_s[3];
    for (int e = tid; e < 3584; e += 256){
        int p = e / 56, oc = e - p*56;
        float base = we_s[oc*3+0]*(float)(p>>3) + we_s[oc*3+1]*(float)(p&7) + be_s[oc];
        float w2 = we_s[oc*3+2];
        float t[4];
        t[0] = (lrelu(base + w2*(hist_s[0*64+p]/total)) - m0) * i0;
        t[1] = (lrelu(base + w2*(hist_s[1*64+p]/total)) - m1) * i1;
        t[2] = (lrelu(base + w2*(hist_s[2*64+p]/total)) - m2) * i2;
        t[3] = (lrelu(base + w2*(hist_s[3*64+p]/total)) - m3) * i3;
        float4* dst = (float4*)&dZg[((size_t)((b*64+p)*56+oc))*16];
        #pragma unroll
        for (int m4 = 0; m4 < 4; m4++){
            float4 o4;
            int m = m4*4;
            o4.x = lrelu(bc_s[m+0] + wc_s[(m+0)*4]*t[0] + wc_s[(m+0)*4+1]*t[1] + wc_s[(m+0)*4+2]*t[2] + wc_s[(m+0)*4+3]*t[3]);
            o4.y = lrelu(bc_s[m+1] + wc_s[(m+1)*4]*t[0] + wc_s[(m+1)*4+1]*t[1] + wc_s[(m+1)*4+2]*t[2] + wc_s[(m+1)*4+3]*t[3]);
            o4.z = lrelu(bc_s[m+2] + wc_s[(m+2)*4]*t[0] + wc_s[(m+2)*4+1]*t[1] + wc_s[(m+2)*4+2]*t[2] + wc_s[(m+2)*4+3]*t[3]);
            o4.w = lrelu(bc_s[m+3] + wc_s[(m+3)*4]*t[0] + wc_s[(m+3)*4+1]*t[1] + wc_s[(m+3)*4+2]*t[2] + wc_s[(m+3)*4+3]*t[3]);
            dst[m4] = o4;
        }
    }
}

// ---- K4: final 3x3 conv 16->1 on upsampled piecewise-constant field (smem staged) ----
__global__ void __launch_bounds__(256) k_final(const float* __restrict__ wf,
                                               const float* __restrict__ bf,
                                               float* __restrict__ out){
    __shared__ float swf[144];
    __shared__ float buf[2][896];
    int h = blockIdx.x, b = blockIdx.y;
    int tid = threadIdx.x;
    if (tid < 144) swf[tid] = wf[tid];
    int g0 = (h >= 1)   ? ((h-1) >> 2) : 0;
    int g1 = (h <= 254) ? ((h+1) >> 2) : 63;
    const float* z0 = &dZg[((size_t)(b*64 + g0))*896];
    const float* z1 = &dZg[((size_t)(b*64 + g1))*896];
    for (int i = tid; i < 896; i += 256){ buf[0][i] = z0[i]; buf[1][i] = z1[i]; }
    __syncthreads();

    int w = tid;
    float acc = bf[0];
    #pragma unroll
    for (int i = -1; i <= 1; i++){
        int hh = h + i;
        if ((unsigned)hh >= 256u) continue;
        int sel = ((hh >> 2) == g0) ? 0 : 1;
        #pragma unroll
        for (int j = -1; j <= 1; j++){
            int ww = w + j;
            if ((unsigned)ww >= 256u) continue;
            int gw = (ww*56) >> 8;
            const float4* zp = (const float4*)&buf[sel][gw*16];
            int wb = (i+1)*3 + (j+1);
            #pragma unroll
            for (int m4 = 0; m4 < 4; m4++){
                float4 z = zp[m4];
                acc += swf[(m4*4+0)*9 + wb] * z.x;
                acc += swf[(m4*4+1)*9 + wb] * z.y;
                acc += swf[(m4*4+2)*9 + wb] * z.z;
                acc += swf[(m4*4+3)*9 + wb] * z.w;
            }
        }
    }
    out[(b<<16) | (h<<8) | w] = lrelu(acc);
}

extern "C" void kernel_launch(void* const* d_in, const int* in_sizes, int n_in,
                              void* d_out, int out_size){
    const float* x    = (const float*)d_in[0];
    const float* we   = (const float*)d_in[1];
    const float* be   = (const float*)d_in[2];
    const float* wc   = (const float*)d_in[3];
    const float* bc   = (const float*)d_in[4];
    const float* wfin = (const float*)d_in[5];
    const float* bfin = (const float*)d_in[6];
    const float* clo  = (const float*)d_in[7];
    const float* chi  = (const float*)d_in[8];
    float* out = (float*)d_out;

    k_pool_minmax<<<dim3(8,16,16), dim3(32,8)>>>(x, clo, chi);
    k_hist       <<<dim3(8,16,16), 256>>>(clo, chi);
    k_grid       <<<16, 256>>>(we, be, wc, bc);
    k_final      <<<dim3(256,16), 256>>>(wfin, bfin, out);
}

// round 5
// speedup vs baseline: 1.4361x; 1.4361x over previous
#include <cuda_runtime.h>
#include <math.h>

#define BATCH 16
#define HW 65536

// ---- scratch (device globals) ----
__device__ float dS[BATCH*HW];
__device__ float dPmn[BATCH*8*128];   // per-block min partials [b][o][blk]
__device__ float dPmx[BATCH*8*128];
__device__ float dHist[4096];
__device__ float dTotal;
__device__ float dZg[BATCH*64*56*16]; // [b][gh][gw][m]

__device__ __forceinline__ float lrelu(float v){ return v >= 0.f ? v : 0.01f*v; }

// ---- K1: fused box-pool (channel sum) + per-orientation clamped-LBP block min/max ----
__global__ void __launch_bounds__(256) k_pool_minmax(const float* __restrict__ x,
                                                     const float* __restrict__ clo,
                                                     const float* __restrict__ chi){
    __shared__ float xs[20][36];
    __shared__ float St[18][34];
    __shared__ float red[8][16];
    int b  = blockIdx.z;
    int h0 = blockIdx.y*16, w0 = blockIdx.x*32;
    int tx = threadIdx.x, ty = threadIdx.y;
    int tid = ty*32 + tx;
    const float* xb = x + (size_t)b*3*HW;

    if (blockIdx.x == 0 && blockIdx.y == 0){
        dHist[b*256 + tid] = 0.f;
        if (b == 0 && tid == 0) dTotal = 0.f;
    }

    for (int i = tid; i < 720; i += 256){
        int r = i/36, c = i - r*36;
        int h = h0-2+r, w = w0-2+c;
        float v = 0.f;
        if ((unsigned)h < 256u && (unsigned)w < 256u){
            int off = (h<<8) | w;
            v = xb[off] + xb[HW+off] + xb[2*HW+off];
        }
        xs[r][c] = v;
    }
    __syncthreads();

    for (int i = tid; i < 612; i += 256){
        int r = i/34, c = i - r*34;
        int h = h0-1+r, w = w0-1+c;
        float s = 0.f;
        if ((unsigned)h < 256u && (unsigned)w < 256u){
            s = (xs[r  ][c] + xs[r  ][c+1] + xs[r  ][c+2]
               + xs[r+1][c] + xs[r+1][c+1] + xs[r+1][c+2]
               + xs[r+2][c] + xs[r+2][c+1] + xs[r+2][c+2]) / 9.0f;
            if (r >= 1 && r < 17 && c >= 1 && c < 33)
                dS[b*HW + (h<<8) + w] = s;
        }
        St[r][c] = s;
    }
    __syncthreads();

    const int DY[8] = {-1,1,-1,1,-1,1,0,0};
    const int DX[8] = {-1,1,0,0,1,-1,1,-1};
    float lo = clo[0], hi = chi[0];
    float mn[8], mx[8];
    #pragma unroll
    for (int o = 0; o < 8; o++){ mn[o] = 3.4e38f; mx[o] = -3.4e38f; }

    #pragma unroll
    for (int ph = 0; ph < 2; ph++){
        int r = ty + ph*8 + 1, c = tx + 1;
        float ctr = St[r][c];
        #pragma unroll
        for (int o = 0; o < 8; o++){
            float v = fminf(fmaxf(ctr - St[r+DY[o]][c+DX[o]], lo), hi);
            mn[o] = fminf(mn[o], v);
            mx[o] = fmaxf(mx[o], v);
        }
    }
    #pragma unroll
    for (int o = 0; o < 8; o++){
        #pragma unroll
        for (int off = 16; off; off >>= 1){
            mn[o] = fminf(mn[o], __shfl_xor_sync(0xffffffffu, mn[o], off));
            mx[o] = fmaxf(mx[o], __shfl_xor_sync(0xffffffffu, mx[o], off));
        }
    }
    int warp = tid >> 5, lane = tid & 31;
    if (lane == 0){
        #pragma unroll
        for (int o = 0; o < 8; o++){ red[warp][o] = mn[o]; red[warp][8+o] = mx[o]; }
    }
    __syncthreads();
    int blk = blockIdx.y*8 + blockIdx.x;
    if (tid < 16){
        if (tid < 8){
            float v = red[0][tid];
            #pragma unroll
            for (int w2 = 1; w2 < 8; w2++) v = fminf(v, red[w2][tid]);
            dPmn[(b*8 + tid)*128 + blk] = v;
        } else {
            float v = red[0][tid];
            #pragma unroll
            for (int w2 = 1; w2 < 8; w2++) v = fmaxf(v, red[w2][tid]);
            dPmx[(b*8 + tid - 8)*128 + blk] = v;
        }
    }
}

// ---- K2: product histogram + global total; reduces minmax partials inline ----
__global__ void __launch_bounds__(256) k_hist(const float* __restrict__ clo,
                                              const float* __restrict__ chi){
    __shared__ float St[18][34];
    __shared__ float sh[8][256];
    __shared__ float lv[8][8];
    __shared__ float smn[8], sscale[8];
    __shared__ float rawmn[8], rawmx[8];
    __shared__ float redt[8];
    int b  = blockIdx.z;
    int h0 = blockIdx.y*16, w0 = blockIdx.x*32;
    int tid = threadIdx.x;
    int warp = tid >> 5, lane = tid & 31;
    const float* Sb = dS + b*HW;

    {
        const float* pmn = &dPmn[(b*8 + warp)*128];
        const float* pmx = &dPmx[(b*8 + warp)*128];
        float mn = fminf(fminf(pmn[lane], pmn[lane+32]), fminf(pmn[lane+64], pmn[lane+96]));
        float mx = fmaxf(fmaxf(pmx[lane], pmx[lane+32]), fmaxf(pmx[lane+64], pmx[lane+96]));
        #pragma unroll
        for (int off = 16; off; off >>= 1){
            mn = fminf(mn, __shfl_xor_sync(0xffffffffu, mn, off));
            mx = fmaxf(mx, __shfl_xor_sync(0xffffffffu, mx, off));
        }
        if (lane == 0){ rawmn[warp] = mn; rawmx[warp] = mx; }
    }

    for (int i = tid; i < 612; i += 256){
        int r = i/34, c = i - r*34;
        int h = h0-1+r, w = w0-1+c;
        St[r][c] = ((unsigned)h < 256u && (unsigned)w < 256u) ? Sb[(h<<8)+w] : 0.f;
    }
    for (int i = tid; i < 2048; i += 256) ((float*)sh)[i] = 0.f;
    __syncthreads();

    if (tid < 64){
        int o = tid >> 3, q = tid & 7;
        float mnv = rawmn[o], mxv = rawmx[o];
        float r = mxv - mnv;
        lv[o][q] = __fadd_rn(mnv, __fmul_rn(r, q*0.125f));
        if (q == 0){ smn[o] = mnv; sscale[o] = (r > 0.f) ? 8.0f/r : 0.f; }
    }
    __syncthreads();

    const int DY[8] = {-1,1,-1,1,-1,1,0,0};
    const int DX[8] = {-1,1,0,0,1,-1,1,-1};
    float lo = clo[0], hic = chi[0];
    int tx = tid & 31, ty = tid >> 5;

    #pragma unroll
    for (int ph = 0; ph < 2; ph++){
        int r = ty + ph*8 + 1, c = tx + 1;
        float ctr = St[r][c];
        float vv[8]; int qq[8]; unsigned tie = 0;
        #pragma unroll
        for (int o = 0; o < 8; o++){
            float v = fminf(fmaxf(ctr - St[r+DY[o]][c+DX[o]], lo), hic);
            float f = (v - smn[o]) * sscale[o];
            int q = (int)f; q = q < 0 ? 0 : (q > 7 ? 7 : q);
            if (q < 7 && v >= lv[o][q+1]) q++;
            if (q < 7 && v >= lv[o][q+1]) q++;
            if (q > 0 && v <  lv[o][q])   q--;
            if (q > 0 && v <  lv[o][q])   q--;
            vv[o] = v; qq[o] = q;
            if (q > 0 && v == lv[o][q]) tie |= 1u << o;
        }
        #pragma unroll
        for (int g = 0; g < 4; g++){
            float prod = vv[2*g] * vv[2*g+1];
            int qi = qq[2*g], qj = qq[2*g+1];
            atomicAdd(&sh[warp][g*64 + qi*8 + qj], prod);
            if (tie & (3u << (2*g))){
                if (tie & (1u << (2*g)))   atomicAdd(&sh[warp][g*64 + (qi-1)*8 + qj], prod);
                if (tie & (1u << (2*g+1))) atomicAdd(&sh[warp][g*64 + qi*8 + (qj-1)], prod);
                if (((tie >> (2*g)) & 3u) == 3u)
                                           atomicAdd(&sh[warp][g*64 + (qi-1)*8 + (qj-1)], prod);
            }
        }
    }
    __syncthreads();

    float s;
    {
        int g = tid >> 6, bin = tid & 63;
        s = sh[0][g*64+bin] + sh[1][g*64+bin] + sh[2][g*64+bin] + sh[3][g*64+bin]
          + sh[4][g*64+bin] + sh[5][g*64+bin] + sh[6][g*64+bin] + sh[7][g*64+bin];
        atomicAdd(&dHist[(b*4+g)*64 + bin], s);
    }
    #pragma unroll
    for (int off = 16; off; off >>= 1) s += __shfl_xor_sync(0xffffffffu, s, off);
    if (lane == 0) redt[warp] = s;
    __syncthreads();
    if (tid == 0){
        float t = 0.f;
        #pragma unroll
        for (int w2 = 0; w2 < 8; w2++) t += redt[w2];
        atomicAdd(&dTotal, t);
    }
}

// ---- K3: fused expand-conv + instance-norm stats + normalized 4->16 conv ----
__global__ void __launch_bounds__(256) k_grid(const float* __restrict__ we,
                                              const float* __restrict__ be,
                                              const float* __restrict__ wc,
                                              const float* __restrict__ bc){
    __shared__ float hist_s[256];
    __shared__ float we_s[168], be_s[56], wc_s[64], bc_s[16];
    __shared__ float sred[8][8];
    __shared__ float mean_s[4], inv_s[4];
    int b = blockIdx.x;
    int tid = threadIdx.x;
    int warp = tid >> 5, lane = tid & 31;

    hist_s[tid] = dHist[b*256 + tid];
    if (tid < 168) we_s[tid] = we[tid];
    if (tid < 56)  be_s[tid] = be[tid];
    if (tid < 64)  wc_s[tid] = wc[tid];
    if (tid < 16)  bc_s[tid] = bc[tid];
    __syncthreads();
    float total = dTotal;

    float s[4] = {0,0,0,0}, sq[4] = {0,0,0,0};
    for (int e = tid; e < 3584; e += 256){
        int p = e / 56, oc = e - p*56;
        int cnt = (((oc+1)*256 + 55)/56) - ((oc*256 + 55)/56);
        float wgt = (float)(cnt*4);
        float base = we_s[oc*3+0]*(float)(p>>3) + we_s[oc*3+1]*(float)(p&7) + be_s[oc];
        float w2 = we_s[oc*3+2];
        #pragma unroll
        for (int g = 0; g < 4; g++){
            float hn = hist_s[g*64+p] / total;
            float y = lrelu(base + w2*hn);
            s[g]  += y*wgt;
            sq[g] += y*y*wgt;
        }
    }
    #pragma unroll
    for (int g = 0; g < 4; g++){
        #pragma unroll
        for (int off = 16; off; off >>= 1){
            s[g]  += __shfl_xor_sync(0xffffffffu, s[g],  off);
            sq[g] += __shfl_xor_sync(0xffffffffu, sq[g], off);
        }
    }
    if (lane == 0){
        #pragma unroll
        for (int g = 0; g < 4; g++){ sred[warp][g] = s[g]; sred[warp][4+g] = sq[g]; }
    }
    __syncthreads();
    if (tid < 4){
        float ts = 0.f, tq = 0.f;
        #pragma unroll
        for (int w2 = 0; w2 < 8; w2++){ ts += sred[w2][tid]; tq += sred[w2][4+tid]; }
        float mean = ts / 65536.f;
        float var  = tq / 65536.f - mean*mean;
        mean_s[tid] = mean;
        inv_s[tid]  = 1.f / sqrtf(fmaxf(var, 0.f) + 1e-5f);
    }
    __syncthreads();

    float m0 = mean_s[0], m1 = mean_s[1], m2 = mean_s[2], m3 = mean_s[3];
    float i0 = inv_s[0],  i1 = inv_s[1],  i2 = inv_s[2],  i3 = inv_s[3];
    for (int e = tid; e < 3584; e += 256){
        int p = e / 56, oc = e - p*56;
        float base = we_s[oc*3+0]*(float)(p>>3) + we_s[oc*3+1]*(float)(p&7) + be_s[oc];
        float w2 = we_s[oc*3+2];
        float t[4];
        t[0] = (lrelu(base + w2*(hist_s[0*64+p]/total)) - m0) * i0;
        t[1] = (lrelu(base + w2*(hist_s[1*64+p]/total)) - m1) * i1;
        t[2] = (lrelu(base + w2*(hist_s[2*64+p]/total)) - m2) * i2;
        t[3] = (lrelu(base + w2*(hist_s[3*64+p]/total)) - m3) * i3;
        float4* dst = (float4*)&dZg[((size_t)((b*64+p)*56+oc))*16];
        #pragma unroll
        for (int m4 = 0; m4 < 4; m4++){
            float4 o4;
            int m = m4*4;
            o4.x = lrelu(bc_s[m+0] + wc_s[(m+0)*4]*t[0] + wc_s[(m+0)*4+1]*t[1] + wc_s[(m+0)*4+2]*t[2] + wc_s[(m+0)*4+3]*t[3]);
            o4.y = lrelu(bc_s[m+1] + wc_s[(m+1)*4]*t[0] + wc_s[(m+1)*4+1]*t[1] + wc_s[(m+1)*4+2]*t[2] + wc_s[(m+1)*4+3]*t[3]);
            o4.z = lrelu(bc_s[m+2] + wc_s[(m+2)*4]*t[0] + wc_s[(m+2)*4+1]*t[1] + wc_s[(m+2)*4+2]*t[2] + wc_s[(m+2)*4+3]*t[3]);
            o4.w = lrelu(bc_s[m+3] + wc_s[(m+3)*4]*t[0] + wc_s[(m+3)*4+1]*t[1] + wc_s[(m+3)*4+2]*t[2] + wc_s[(m+3)*4+3]*t[3]);
            dst[m4] = o4;
        }
    }
}

// ---- K4: final 3x3 conv via per-grid-cell tap tables.
// One block per (gh-group t, batch). 4 output rows; rows 4t+1 and 4t+2 are identical.
__global__ void __launch_bounds__(256) k_final(const float* __restrict__ wf,
                                               const float* __restrict__ bf,
                                               float* __restrict__ out){
    __shared__ float swf[144];
    __shared__ float ztop[896], zmid[896], zbot[896];
    __shared__ float u[3][168];      // [tbl][gw*3+j]
    int t = blockIdx.x, b = blockIdx.y;
    int tid = threadIdx.x;
    if (tid < 144) swf[tid] = wf[tid];
    const float* zrow = &dZg[((size_t)(b*64 + t))*896];
    for (int i = tid; i < 896; i += 256){
        zmid[i] = zrow[i];
        ztop[i] = (t > 0)  ? zrow[i - 896] : 0.f;
        zbot[i] = (t < 63) ? zrow[i + 896] : 0.f;
    }
    __syncthreads();

    // build tap tables: u[tbl][gw][j]
    for (int e = tid; e < 504; e += 256){
        int tbl = e / 168, rem = e - tbl*168;
        int gw = rem / 3, j = rem - gw*3;
        const float* zc = &zmid[gw*16];
        float acc = 0.f;
        if (tbl == 0){                       // row 4t: i=-1 -> t-1 (skip at t=0), i=0,1 -> t
            const float* zt2 = &ztop[gw*16];
            bool hasT = (t > 0);
            #pragma unroll
            for (int m = 0; m < 16; m++){
                float w01 = swf[m*9+3+j] + swf[m*9+6+j];
                acc += w01 * zc[m];
                if (hasT) acc += swf[m*9+j] * zt2[m];
            }
        } else if (tbl == 1){                // rows 4t+1 / 4t+2: all -> t
            #pragma unroll
            for (int m = 0; m < 16; m++)
                acc += (swf[m*9+j] + swf[m*9+3+j] + swf[m*9+6+j]) * zc[m];
        } else {                             // row 4t+3: i=-1,0 -> t, i=+1 -> t+1 (skip at t=63)
            const float* zb2 = &zbot[gw*16];
            bool hasB = (t < 63);
            #pragma unroll
            for (int m = 0; m < 16; m++){
                acc += (swf[m*9+j] + swf[m*9+3+j]) * zc[m];
                if (hasB) acc += swf[m*9+6+j] * zb2[m];
            }
        }
        u[tbl][rem] = acc;
    }
    __syncthreads();

    int w = tid;
    int gwC = (w*56) >> 8;
    int gwL = ((w-1)*56) >> 8;               // valid only if w>0
    int gwR = ((w+1)*56) >> 8;               // valid only if w<255
    float base = bf[0];
    size_t o0 = ((size_t)b << 16) | ((size_t)(t*4) << 8) | (size_t)w;

    #pragma unroll
    for (int tbl = 0; tbl < 3; tbl++){
        float acc = base + u[tbl][gwC*3 + 1];
        if (w > 0)   acc += u[tbl][gwL*3 + 0];
        if (w < 255) acc += u[tbl][gwR*3 + 2];
        float o = lrelu(acc);
        if (tbl == 0)      out[o0]            = o;
        else if (tbl == 1){ out[o0 + 256]     = o;
                            out[o0 + 512]     = o; }
        else               out[o0 + 768]      = o;
    }
}

extern "C" void kernel_launch(void* const* d_in, const int* in_sizes, int n_in,
                              void* d_out, int out_size){
    const float* x    = (const float*)d_in[0];
    const float* we   = (const float*)d_in[1];
    const float* be   = (const float*)d_in[2];
    const float* wc   = (const float*)d_in[3];
    const float* bc   = (const float*)d_in[4];
    const float* wfin = (const float*)d_in[5];
    const float* bfin = (const float*)d_in[6];
    const float* clo  = (const float*)d_in[7];
    const float* chi  = (const float*)d_in[8];
    float* out = (float*)d_out;

    k_pool_minmax<<<dim3(8,16,16), dim3(32,8)>>>(x, clo, chi);
    k_hist       <<<dim3(8,16,16), 256>>>(clo, chi);
    k_grid       <<<16, 256>>>(we, be, wc, bc);
    k_final      <<<dim3(64,16), 256>>>(wfin, bfin, out);
}

// round 6
// speedup vs baseline: 1.5308x; 1.0659x over previous
#include <cuda_runtime.h>
#include <math.h>

#define BATCH 16
#define HW 65536

// ---- scratch (device globals) ----
__device__ float dS[BATCH*HW];
__device__ float dPmn[BATCH*8*128];   // per-block min partials [b][o][blk]
__device__ float dPmx[BATCH*8*128];
__device__ float dHist[4096];
__device__ float dTotal;
// per-cell, per-weight-row contraction: r_i[j] = sum_m z[m]*wf[m][3i+j]
// layout: [b][gh][gw*3+j]  (168 floats per (b,gh) row)
__device__ float dR0[BATCH*64*168];
__device__ float dR1[BATCH*64*168];
__device__ float dR2[BATCH*64*168];

__device__ __forceinline__ float lrelu(float v){ return v >= 0.f ? v : 0.01f*v; }

// ---- K1: fused box-pool (channel sum) + per-orientation clamped-LBP block min/max ----
__global__ void __launch_bounds__(256) k_pool_minmax(const float* __restrict__ x,
                                                     const float* __restrict__ clo,
                                                     const float* __restrict__ chi){
    __shared__ float xs[20][36];
    __shared__ float St[18][34];
    __shared__ float red[8][16];
    int b  = blockIdx.z;
    int h0 = blockIdx.y*16, w0 = blockIdx.x*32;
    int tx = threadIdx.x, ty = threadIdx.y;
    int tid = ty*32 + tx;
    const float* xb = x + (size_t)b*3*HW;

    if (blockIdx.x == 0 && blockIdx.y == 0){
        dHist[b*256 + tid] = 0.f;
        if (b == 0 && tid == 0) dTotal = 0.f;
    }

    for (int i = tid; i < 720; i += 256){
        int r = i/36, c = i - r*36;
        int h = h0-2+r, w = w0-2+c;
        float v = 0.f;
        if ((unsigned)h < 256u && (unsigned)w < 256u){
            int off = (h<<8) | w;
            v = xb[off] + xb[HW+off] + xb[2*HW+off];
        }
        xs[r][c] = v;
    }
    __syncthreads();

    for (int i = tid; i < 612; i += 256){
        int r = i/34, c = i - r*34;
        int h = h0-1+r, w = w0-1+c;
        float s = 0.f;
        if ((unsigned)h < 256u && (unsigned)w < 256u){
            s = (xs[r  ][c] + xs[r  ][c+1] + xs[r  ][c+2]
               + xs[r+1][c] + xs[r+1][c+1] + xs[r+1][c+2]
               + xs[r+2][c] + xs[r+2][c+1] + xs[r+2][c+2]) / 9.0f;
            if (r >= 1 && r < 17 && c >= 1 && c < 33)
                dS[b*HW + (h<<8) + w] = s;
        }
        St[r][c] = s;
    }
    __syncthreads();

    const int DY[8] = {-1,1,-1,1,-1,1,0,0};
    const int DX[8] = {-1,1,0,0,1,-1,1,-1};
    float lo = clo[0], hi = chi[0];
    float mn[8], mx[8];
    #pragma unroll
    for (int o = 0; o < 8; o++){ mn[o] = 3.4e38f; mx[o] = -3.4e38f; }

    #pragma unroll
    for (int ph = 0; ph < 2; ph++){
        int r = ty + ph*8 + 1, c = tx + 1;
        float ctr = St[r][c];
        #pragma unroll
        for (int o = 0; o < 8; o++){
            float v = fminf(fmaxf(ctr - St[r+DY[o]][c+DX[o]], lo), hi);
            mn[o] = fminf(mn[o], v);
            mx[o] = fmaxf(mx[o], v);
        }
    }
    #pragma unroll
    for (int o = 0; o < 8; o++){
        #pragma unroll
        for (int off = 16; off; off >>= 1){
            mn[o] = fminf(mn[o], __shfl_xor_sync(0xffffffffu, mn[o], off));
            mx[o] = fmaxf(mx[o], __shfl_xor_sync(0xffffffffu, mx[o], off));
        }
    }
    int warp = tid >> 5, lane = tid & 31;
    if (lane == 0){
        #pragma unroll
        for (int o = 0; o < 8; o++){ red[warp][o] = mn[o]; red[warp][8+o] = mx[o]; }
    }
    __syncthreads();
    int blk = blockIdx.y*8 + blockIdx.x;
    if (tid < 16){
        if (tid < 8){
            float v = red[0][tid];
            #pragma unroll
            for (int w2 = 1; w2 < 8; w2++) v = fminf(v, red[w2][tid]);
            dPmn[(b*8 + tid)*128 + blk] = v;
        } else {
            float v = red[0][tid];
            #pragma unroll
            for (int w2 = 1; w2 < 8; w2++) v = fmaxf(v, red[w2][tid]);
            dPmx[(b*8 + tid - 8)*128 + blk] = v;
        }
    }
}

// ---- K2: product histogram + global total; reduces minmax partials inline ----
__global__ void __launch_bounds__(256) k_hist(const float* __restrict__ clo,
                                              const float* __restrict__ chi){
    __shared__ float St[18][34];
    __shared__ float sh[8][256];
    __shared__ float lv[8][8];
    __shared__ float smn[8], sscale[8];
    __shared__ float rawmn[8], rawmx[8];
    __shared__ float redt[8];
    int b  = blockIdx.z;
    int h0 = blockIdx.y*16, w0 = blockIdx.x*32;
    int tid = threadIdx.x;
    int warp = tid >> 5, lane = tid & 31;
    const float* Sb = dS + b*HW;

    {
        const float* pmn = &dPmn[(b*8 + warp)*128];
        const float* pmx = &dPmx[(b*8 + warp)*128];
        float mn = fminf(fminf(pmn[lane], pmn[lane+32]), fminf(pmn[lane+64], pmn[lane+96]));
        float mx = fmaxf(fmaxf(pmx[lane], pmx[lane+32]), fmaxf(pmx[lane+64], pmx[lane+96]));
        #pragma unroll
        for (int off = 16; off; off >>= 1){
            mn = fminf(mn, __shfl_xor_sync(0xffffffffu, mn, off));
            mx = fmaxf(mx, __shfl_xor_sync(0xffffffffu, mx, off));
        }
        if (lane == 0){ rawmn[warp] = mn; rawmx[warp] = mx; }
    }

    for (int i = tid; i < 612; i += 256){
        int r = i/34, c = i - r*34;
        int h = h0-1+r, w = w0-1+c;
        St[r][c] = ((unsigned)h < 256u && (unsigned)w < 256u) ? Sb[(h<<8)+w] : 0.f;
    }
    for (int i = tid; i < 2048; i += 256) ((float*)sh)[i] = 0.f;
    __syncthreads();

    if (tid < 64){
        int o = tid >> 3, q = tid & 7;
        float mnv = rawmn[o], mxv = rawmx[o];
        float r = mxv - mnv;
        lv[o][q] = __fadd_rn(mnv, __fmul_rn(r, q*0.125f));
        if (q == 0){ smn[o] = mnv; sscale[o] = (r > 0.f) ? 8.0f/r : 0.f; }
    }
    __syncthreads();

    const int DY[8] = {-1,1,-1,1,-1,1,0,0};
    const int DX[8] = {-1,1,0,0,1,-1,1,-1};
    float lo = clo[0], hic = chi[0];
    int tx = tid & 31, ty = tid >> 5;

    #pragma unroll
    for (int ph = 0; ph < 2; ph++){
        int r = ty + ph*8 + 1, c = tx + 1;
        float ctr = St[r][c];
        float vv[8]; int qq[8]; unsigned tie = 0;
        #pragma unroll
        for (int o = 0; o < 8; o++){
            float v = fminf(fmaxf(ctr - St[r+DY[o]][c+DX[o]], lo), hic);
            float f = (v - smn[o]) * sscale[o];
            int q = (int)f; q = q < 0 ? 0 : (q > 7 ? 7 : q);
            if (q < 7 && v >= lv[o][q+1]) q++;
            if (q < 7 && v >= lv[o][q+1]) q++;
            if (q > 0 && v <  lv[o][q])   q--;
            if (q > 0 && v <  lv[o][q])   q--;
            vv[o] = v; qq[o] = q;
            if (q > 0 && v == lv[o][q]) tie |= 1u << o;
        }
        #pragma unroll
        for (int g = 0; g < 4; g++){
            float prod = vv[2*g] * vv[2*g+1];
            int qi = qq[2*g], qj = qq[2*g+1];
            atomicAdd(&sh[warp][g*64 + qi*8 + qj], prod);
            if (tie & (3u << (2*g))){
                if (tie & (1u << (2*g)))   atomicAdd(&sh[warp][g*64 + (qi-1)*8 + qj], prod);
                if (tie & (1u << (2*g+1))) atomicAdd(&sh[warp][g*64 + qi*8 + (qj-1)], prod);
                if (((tie >> (2*g)) & 3u) == 3u)
                                           atomicAdd(&sh[warp][g*64 + (qi-1)*8 + (qj-1)], prod);
            }
        }
    }
    __syncthreads();

    float s;
    {
        int g = tid >> 6, bin = tid & 63;
        s = sh[0][g*64+bin] + sh[1][g*64+bin] + sh[2][g*64+bin] + sh[3][g*64+bin]
          + sh[4][g*64+bin] + sh[5][g*64+bin] + sh[6][g*64+bin] + sh[7][g*64+bin];
        atomicAdd(&dHist[(b*4+g)*64 + bin], s);
    }
    #pragma unroll
    for (int off = 16; off; off >>= 1) s += __shfl_xor_sync(0xffffffffu, s, off);
    if (lane == 0) redt[warp] = s;
    __syncthreads();
    if (tid == 0){
        float t = 0.f;
        #pragma unroll
        for (int w2 = 0; w2 < 8; w2++) t += redt[w2];
        atomicAdd(&dTotal, t);
    }
}

// ---- K3: expand-conv + instance-norm + 4->16 conv + wf row-contraction ----
__global__ void __launch_bounds__(256) k_grid(const float* __restrict__ we,
                                              const float* __restrict__ be,
                                              const float* __restrict__ wc,
                                              const float* __restrict__ bc,
                                              const float* __restrict__ wf){
    __shared__ float hist_s[256];
    __shared__ float we_s[168], be_s[56], wc_s[64], bc_s[16], wf_s[144];
    __shared__ float sred[8][8];
    __shared__ float mean_s[4], inv_s[4];
    int b = blockIdx.x;
    int tid = threadIdx.x;
    int warp = tid >> 5, lane = tid & 31;

    hist_s[tid] = dHist[b*256 + tid];
    if (tid < 168) we_s[tid] = we[tid];
    if (tid < 56)  be_s[tid] = be[tid];
    if (tid < 64)  wc_s[tid] = wc[tid];
    if (tid < 16)  bc_s[tid] = bc[tid];
    if (tid < 144) wf_s[tid] = wf[tid];
    __syncthreads();
    float total = dTotal;

    float s[4] = {0,0,0,0}, sq[4] = {0,0,0,0};
    for (int e = tid; e < 3584; e += 256){
        int p = e / 56, oc = e - p*56;
        int cnt = (((oc+1)*256 + 55)/56) - ((oc*256 + 55)/56);
        float wgt = (float)(cnt*4);
        float base = we_s[oc*3+0]*(float)(p>>3) + we_s[oc*3+1]*(float)(p&7) + be_s[oc];
        float w2 = we_s[oc*3+2];
        #pragma unroll
        for (int g = 0; g < 4; g++){
            float hn = hist_s[g*64+p] / total;
            float y = lrelu(base + w2*hn);
            s[g]  += y*wgt;
            sq[g] += y*y*wgt;
        }
    }
    #pragma unroll
    for (int g = 0; g < 4; g++){
        #pragma unroll
        for (int off = 16; off; off >>= 1){
            s[g]  += __shfl_xor_sync(0xffffffffu, s[g],  off);
            sq[g] += __shfl_xor_sync(0xffffffffu, sq[g], off);
        }
    }
    if (lane == 0){
        #pragma unroll
        for (int g = 0; g < 4; g++){ sred[warp][g] = s[g]; sred[warp][4+g] = sq[g]; }
    }
    __syncthreads();
    if (tid < 4){
        float ts = 0.f, tq = 0.f;
        #pragma unroll
        for (int w2 = 0; w2 < 8; w2++){ ts += sred[w2][tid]; tq += sred[w2][4+tid]; }
        float mean = ts / 65536.f;
        float var  = tq / 65536.f - mean*mean;
        mean_s[tid] = mean;
        inv_s[tid]  = 1.f / sqrtf(fmaxf(var, 0.f) + 1e-5f);
    }
    __syncthreads();

    float m0 = mean_s[0], m1 = mean_s[1], m2 = mean_s[2], m3 = mean_s[3];
    float i0 = inv_s[0],  i1 = inv_s[1],  i2 = inv_s[2],  i3 = inv_s[3];
    for (int e = tid; e < 3584; e += 256){
        int p = e / 56, oc = e - p*56;
        float base = we_s[oc*3+0]*(float)(p>>3) + we_s[oc*3+1]*(float)(p&7) + be_s[oc];
        float w2 = we_s[oc*3+2];
        float t[4];
        t[0] = (lrelu(base + w2*(hist_s[0*64+p]/total)) - m0) * i0;
        t[1] = (lrelu(base + w2*(hist_s[1*64+p]/total)) - m1) * i1;
        t[2] = (lrelu(base + w2*(hist_s[2*64+p]/total)) - m2) * i2;
        t[3] = (lrelu(base + w2*(hist_s[3*64+p]/total)) - m3) * i3;
        float r[3][3] = {{0,0,0},{0,0,0},{0,0,0}};
        #pragma unroll
        for (int m = 0; m < 16; m++){
            float zm = lrelu(bc_s[m] + wc_s[m*4]*t[0] + wc_s[m*4+1]*t[1]
                                     + wc_s[m*4+2]*t[2] + wc_s[m*4+3]*t[3]);
            #pragma unroll
            for (int i = 0; i < 3; i++){
                r[i][0] += zm * wf_s[m*9 + i*3 + 0];
                r[i][1] += zm * wf_s[m*9 + i*3 + 1];
                r[i][2] += zm * wf_s[m*9 + i*3 + 2];
            }
        }
        int idx = b*64*168 + p*168 + oc*3;
        dR0[idx] = r[0][0]; dR0[idx+1] = r[0][1]; dR0[idx+2] = r[0][2];
        dR1[idx] = r[1][0]; dR1[idx+1] = r[1][1]; dR1[idx+2] = r[1][2];
        dR2[idx] = r[2][0]; dR2[idx+1] = r[2][1]; dR2[idx+2] = r[2][2];
    }
}

// ---- K4: final conv — assemble tap tables from precomputed row-sums, then 3 LDS/px ----
__global__ void __launch_bounds__(256) k_final(const float* __restrict__ bf,
                                               float* __restrict__ out){
    __shared__ float u[3][168];      // [tbl][gw*3+j]
    int t = blockIdx.x, b = blockIdx.y;
    int tid = threadIdx.x;
    int rowbase = b*64*168 + t*168;

    for (int e = tid; e < 504; e += 256){
        int tbl = e / 168, k = e - tbl*168;
        float acc;
        if (tbl == 0){            // row 4t: r0(t-1) + r1(t) + r2(t)
            acc = dR1[rowbase + k] + dR2[rowbase + k];
            if (t > 0) acc += dR0[rowbase - 168 + k];
        } else if (tbl == 1){     // rows 4t+1/4t+2: r0(t)+r1(t)+r2(t)
            acc = dR0[rowbase + k] + dR1[rowbase + k] + dR2[rowbase + k];
        } else {                  // row 4t+3: r0(t)+r1(t) + r2(t+1)
            acc = dR0[rowbase + k] + dR1[rowbase + k];
            if (t < 63) acc += dR2[rowbase + 168 + k];
        }
        u[tbl][k] = acc;
    }
    __syncthreads();

    int w = tid;
    int gwC = (w*56) >> 8;
    int gwL = ((w-1)*56) >> 8;
    int gwR = ((w+1)*56) >> 8;
    float base = bf[0];
    size_t o0 = ((size_t)b << 16) | ((size_t)(t*4) << 8) | (size_t)w;

    #pragma unroll
    for (int tbl = 0; tbl < 3; tbl++){
        float acc = base + u[tbl][gwC*3 + 1];
        if (w > 0)   acc += u[tbl][gwL*3 + 0];
        if (w < 255) acc += u[tbl][gwR*3 + 2];
        float o = lrelu(acc);
        if (tbl == 0)      out[o0]        = o;
        else if (tbl == 1){ out[o0 + 256] = o;
                            out[o0 + 512] = o; }
        else               out[o0 + 768]  = o;
    }
}

extern "C" void kernel_launch(void* const* d_in, const int* in_sizes, int n_in,
                              void* d_out, int out_size){
    const float* x    = (const float*)d_in[0];
    const float* we   = (const float*)d_in[1];
    const float* be   = (const float*)d_in[2];
    const float* wc   = (const float*)d_in[3];
    const float* bc   = (const float*)d_in[4];
    const float* wfin = (const float*)d_in[5];
    const float* bfin = (const float*)d_in[6];
    const float* clo  = (const float*)d_in[7];
    const float* chi  = (const float*)d_in[8];
    float* out = (float*)d_out;

    k_pool_minmax<<<dim3(8,16,16), dim3(32,8)>>>(x, clo, chi);
    k_hist       <<<dim3(8,16,16), 256>>>(clo, chi);
    k_grid       <<<16, 256>>>(we, be, wc, bc, wfin);
    k_final      <<<dim3(64,16), 256>>>(bfin, out);
}

// round 7
// speedup vs baseline: 1.8118x; 1.1836x over previous
#include <cuda_runtime.h>
#include <math.h>

#define BATCH 16
#define HW 65536

// ---- scratch (device globals) ----
__device__ float dS[BATCH*HW];
__device__ float dPmn[BATCH*8*128];
__device__ float dPmx[BATCH*8*128];
__device__ float dHist[4096];
__device__ float dTotal;
__device__ float dR0[BATCH*64*168];
__device__ float dR1[BATCH*64*168];
__device__ float dR2[BATCH*64*168];

__device__ __forceinline__ float lrelu(float v){ return v >= 0.f ? v : 0.01f*v; }

// ---- K1: fused box-pool (channel sum) + per-orientation clamped-LBP block min/max ----
// Vectorized staging: tile cols based at w0-4 so every float4 is fully in- or out-of-bounds.
__global__ void __launch_bounds__(256) k_pool_minmax(const float* __restrict__ x,
                                                     const float* __restrict__ clo,
                                                     const float* __restrict__ chi){
    __shared__ float xs[20][40];   // rows h0-2..h0+17, cols w0-4..w0+35
    __shared__ float St[18][34];   // S(h0-1+r, w0-1+c)
    __shared__ float red[8][16];
    int b  = blockIdx.z;
    int h0 = blockIdx.y*16, w0 = blockIdx.x*32;
    int tx = threadIdx.x, ty = threadIdx.y;
    int tid = ty*32 + tx;
    const float* xb = x + (size_t)b*3*HW;

    if (blockIdx.x == 0 && blockIdx.y == 0){
        dHist[b*256 + tid] = 0.f;
        if (b == 0 && tid == 0) dTotal = 0.f;
    }

    // stage xs: 200 float4 slots
    for (int i = tid; i < 200; i += 256){
        int r = i/10, c4 = i - r*10;
        int gh = h0-2+r, gw = w0-4+c4*4;
        float4 v = make_float4(0.f,0.f,0.f,0.f);
        if ((unsigned)gh < 256u && gw >= 0 && gw <= 252){
            const float* p0 = xb + (gh<<8) + gw;
            float4 a = *(const float4*)p0;
            float4 bb = *(const float4*)(p0 + HW);
            float4 cc = *(const float4*)(p0 + 2*HW);
            v.x = a.x+bb.x+cc.x; v.y = a.y+bb.y+cc.y;
            v.z = a.z+bb.z+cc.z; v.w = a.w+bb.w+cc.w;
        }
        xs[r][c4*4+0] = v.x; xs[r][c4*4+1] = v.y;
        xs[r][c4*4+2] = v.z; xs[r][c4*4+3] = v.w;
    }
    __syncthreads();

    // St[r][c] = box3x3 of xs rows r..r+2, cols c+2..c+4; zero when S-position OOB
    for (int i = tid; i < 612; i += 256){
        int r = i/34, c = i - r*34;
        int h = h0-1+r, w = w0-1+c;
        float s = 0.f;
        if ((unsigned)h < 256u && (unsigned)w < 256u){
            s = (xs[r  ][c+2] + xs[r  ][c+3] + xs[r  ][c+4]
               + xs[r+1][c+2] + xs[r+1][c+3] + xs[r+1][c+4]
               + xs[r+2][c+2] + xs[r+2][c+3] + xs[r+2][c+4]) / 9.0f;
        }
        St[r][c] = s;
    }
    __syncthreads();

    // write dS interior with float4 (unaligned smem reads, aligned gmem writes)
    for (int i = tid; i < 128; i += 256){
        int r = i >> 3, c4 = i & 7;
        float4 v;
        v.x = St[r+1][1+c4*4]; v.y = St[r+1][2+c4*4];
        v.z = St[r+1][3+c4*4]; v.w = St[r+1][4+c4*4];
        *(float4*)&dS[b*HW + ((h0+r)<<8) + w0 + c4*4] = v;
    }

    const int DY[8] = {-1,1,-1,1,-1,1,0,0};
    const int DX[8] = {-1,1,0,0,1,-1,1,-1};
    float lo = clo[0], hi = chi[0];
    float mn[8], mx[8];
    #pragma unroll
    for (int o = 0; o < 8; o++){ mn[o] = 3.4e38f; mx[o] = -3.4e38f; }

    #pragma unroll
    for (int ph = 0; ph < 2; ph++){
        int r = ty + ph*8 + 1, c = tx + 1;
        float ctr = St[r][c];
        #pragma unroll
        for (int o = 0; o < 8; o++){
            float v = fminf(fmaxf(ctr - St[r+DY[o]][c+DX[o]], lo), hi);
            mn[o] = fminf(mn[o], v);
            mx[o] = fmaxf(mx[o], v);
        }
    }
    #pragma unroll
    for (int o = 0; o < 8; o++){
        #pragma unroll
        for (int off = 16; off; off >>= 1){
            mn[o] = fminf(mn[o], __shfl_xor_sync(0xffffffffu, mn[o], off));
            mx[o] = fmaxf(mx[o], __shfl_xor_sync(0xffffffffu, mx[o], off));
        }
    }
    int warp = tid >> 5, lane = tid & 31;
    if (lane == 0){
        #pragma unroll
        for (int o = 0; o < 8; o++){ red[warp][o] = mn[o]; red[warp][8+o] = mx[o]; }
    }
    __syncthreads();
    int blk = blockIdx.y*8 + blockIdx.x;
    if (tid < 16){
        if (tid < 8){
            float v = red[0][tid];
            #pragma unroll
            for (int w2 = 1; w2 < 8; w2++) v = fminf(v, red[w2][tid]);
            dPmn[(b*8 + tid)*128 + blk] = v;
        } else {
            float v = red[0][tid];
            #pragma unroll
            for (int w2 = 1; w2 < 8; w2++) v = fmaxf(v, red[w2][tid]);
            dPmx[(b*8 + tid - 8)*128 + blk] = v;
        }
    }
}

// ---- K2: product histogram + global total; vectorized S staging ----
__global__ void __launch_bounds__(256) k_hist(const float* __restrict__ clo,
                                              const float* __restrict__ chi){
    __shared__ float Sh[18][40];     // rows h0-1..h0+16, cols w0-4..w0+35
    __shared__ float sh[8][256];
    __shared__ float lv[8][8];
    __shared__ float smn[8], sscale[8];
    __shared__ float rawmn[8], rawmx[8];
    __shared__ float redt[8];
    int b  = blockIdx.z;
    int h0 = blockIdx.y*16, w0 = blockIdx.x*32;
    int tid = threadIdx.x;
    int warp = tid >> 5, lane = tid & 31;
    const float* Sb = dS + b*HW;

    {
        const float* pmn = &dPmn[(b*8 + warp)*128];
        const float* pmx = &dPmx[(b*8 + warp)*128];
        float mn = fminf(fminf(pmn[lane], pmn[lane+32]), fminf(pmn[lane+64], pmn[lane+96]));
        float mx = fmaxf(fmaxf(pmx[lane], pmx[lane+32]), fmaxf(pmx[lane+64], pmx[lane+96]));
        #pragma unroll
        for (int off = 16; off; off >>= 1){
            mn = fminf(mn, __shfl_xor_sync(0xffffffffu, mn, off));
            mx = fmaxf(mx, __shfl_xor_sync(0xffffffffu, mx, off));
        }
        if (lane == 0){ rawmn[warp] = mn; rawmx[warp] = mx; }
    }

    for (int i = tid; i < 180; i += 256){
        int r = i/10, c4 = i - r*10;
        int gh = h0-1+r, gw = w0-4+c4*4;
        float4 v = make_float4(0.f,0.f,0.f,0.f);
        if ((unsigned)gh < 256u && gw >= 0 && gw <= 252)
            v = *(const float4*)(Sb + (gh<<8) + gw);
        Sh[r][c4*4+0] = v.x; Sh[r][c4*4+1] = v.y;
        Sh[r][c4*4+2] = v.z; Sh[r][c4*4+3] = v.w;
    }
    for (int i = tid; i < 2048; i += 256) ((float*)sh)[i] = 0.f;
    __syncthreads();

    if (tid < 64){
        int o = tid >> 3, q = tid & 7;
        float mnv = rawmn[o], mxv = rawmx[o];
        float r = mxv - mnv;
        lv[o][q] = __fadd_rn(mnv, __fmul_rn(r, q*0.125f));
        if (q == 0){ smn[o] = mnv; sscale[o] = (r > 0.f) ? 8.0f/r : 0.f; }
    }
    __syncthreads();

    const int DY[8] = {-1,1,-1,1,-1,1,0,0};
    const int DX[8] = {-1,1,0,0,1,-1,1,-1};
    int tx = tid & 31, ty = tid >> 5;

    #pragma unroll
    for (int ph = 0; ph < 2; ph++){
        int r = ty + ph*8 + 1, cc = tx + 4;      // center col w0+tx
        float ctr = Sh[r][cc];
        float vv[8]; int qq[8]; unsigned tie = 0;
        float lo = clo[0], hic = chi[0];
        #pragma unroll
        for (int o = 0; o < 8; o++){
            float v = fminf(fmaxf(ctr - Sh[r+DY[o]][cc+DX[o]], lo), hic);
            float f = (v - smn[o]) * sscale[o];
            int q = (int)f; q = q < 0 ? 0 : (q > 7 ? 7 : q);
            if (q < 7 && v >= lv[o][q+1]) q++;
            if (q < 7 && v >= lv[o][q+1]) q++;
            if (q > 0 && v <  lv[o][q])   q--;
            if (q > 0 && v <  lv[o][q])   q--;
            vv[o] = v; qq[o] = q;
            if (q > 0 && v == lv[o][q]) tie |= 1u << o;
        }
        #pragma unroll
        for (int g = 0; g < 4; g++){
            float prod = vv[2*g] * vv[2*g+1];
            int qi = qq[2*g], qj = qq[2*g+1];
            atomicAdd(&sh[warp][g*64 + qi*8 + qj], prod);
            if (tie & (3u << (2*g))){
                if (tie & (1u << (2*g)))   atomicAdd(&sh[warp][g*64 + (qi-1)*8 + qj], prod);
                if (tie & (1u << (2*g+1))) atomicAdd(&sh[warp][g*64 + qi*8 + (qj-1)], prod);
                if (((tie >> (2*g)) & 3u) == 3u)
                                           atomicAdd(&sh[warp][g*64 + (qi-1)*8 + (qj-1)], prod);
            }
        }
    }
    __syncthreads();

    float s;
    {
        int g = tid >> 6, bin = tid & 63;
        s = sh[0][g*64+bin] + sh[1][g*64+bin] + sh[2][g*64+bin] + sh[3][g*64+bin]
          + sh[4][g*64+bin] + sh[5][g*64+bin] + sh[6][g*64+bin] + sh[7][g*64+bin];
        atomicAdd(&dHist[(b*4+g)*64 + bin], s);
    }
    #pragma unroll
    for (int off = 16; off; off >>= 1) s += __shfl_xor_sync(0xffffffffu, s, off);
    if (lane == 0) redt[warp] = s;
    __syncthreads();
    if (tid == 0){
        float t = 0.f;
        #pragma unroll
        for (int w2 = 0; w2 < 8; w2++) t += redt[w2];
        atomicAdd(&dTotal, t);
    }
}

// ---- K3: expand-conv + instance-norm + 4->16 conv + wf row-contraction ----
// 128 blocks: 8 per batch, each recomputes stats (cheap) and handles 1/8 of pass 2.
__global__ void __launch_bounds__(256) k_grid(const float* __restrict__ we,
                                              const float* __restrict__ be,
                                              const float* __restrict__ wc,
                                              const float* __restrict__ bc,
                                              const float* __restrict__ wf){
    __shared__ float hist_s[256];
    __shared__ float we_s[168], be_s[56], wc_s[64], bc_s[16], wf_s[144];
    __shared__ float sred[8][8];
    __shared__ float mean_s[4], inv_s[4];
    int b = blockIdx.x >> 3, q = blockIdx.x & 7;
    int tid = threadIdx.x;
    int warp = tid >> 5, lane = tid & 31;

    hist_s[tid] = dHist[b*256 + tid];
    if (tid < 168) we_s[tid] = we[tid];
    if (tid < 56)  be_s[tid] = be[tid];
    if (tid < 64)  wc_s[tid] = wc[tid];
    if (tid < 16)  bc_s[tid] = bc[tid];
    if (tid < 144) wf_s[tid] = wf[tid];
    __syncthreads();
    float total = dTotal;

    float s[4] = {0,0,0,0}, sq[4] = {0,0,0,0};
    for (int e = tid; e < 3584; e += 256){
        int p = e / 56, oc = e - p*56;
        int cnt = (((oc+1)*256 + 55)/56) - ((oc*256 + 55)/56);
        float wgt = (float)(cnt*4);
        float base = we_s[oc*3+0]*(float)(p>>3) + we_s[oc*3+1]*(float)(p&7) + be_s[oc];
        float w2 = we_s[oc*3+2];
        #pragma unroll
        for (int g = 0; g < 4; g++){
            float hn = hist_s[g*64+p] / total;
            float y = lrelu(base + w2*hn);
            s[g]  += y*wgt;
            sq[g] += y*y*wgt;
        }
    }
    #pragma unroll
    for (int g = 0; g < 4; g++){
        #pragma unroll
        for (int off = 16; off; off >>= 1){
            s[g]  += __shfl_xor_sync(0xffffffffu, s[g],  off);
            sq[g] += __shfl_xor_sync(0xffffffffu, sq[g], off);
        }
    }
    if (lane == 0){
        #pragma unroll
        for (int g = 0; g < 4; g++){ sred[warp][g] = s[g]; sred[warp][4+g] = sq[g]; }
    }
    __syncthreads();
    if (tid < 4){
        float ts = 0.f, tq = 0.f;
        #pragma unroll
        for (int w2 = 0; w2 < 8; w2++){ ts += sred[w2][tid]; tq += sred[w2][4+tid]; }
        float mean = ts / 65536.f;
        float var  = tq / 65536.f - mean*mean;
        mean_s[tid] = mean;
        inv_s[tid]  = 1.f / sqrtf(fmaxf(var, 0.f) + 1e-5f);
    }
    __syncthreads();

    float m0 = mean_s[0], m1 = mean_s[1], m2 = mean_s[2], m3 = mean_s[3];
    float i0 = inv_s[0],  i1 = inv_s[1],  i2 = inv_s[2],  i3 = inv_s[3];
    for (int e = q*448 + tid; e < (q+1)*448; e += 256){
        int p = e / 56, oc = e - p*56;
        float base = we_s[oc*3+0]*(float)(p>>3) + we_s[oc*3+1]*(float)(p&7) + be_s[oc];
        float w2 = we_s[oc*3+2];
        float t[4];
        t[0] = (lrelu(base + w2*(hist_s[0*64+p]/total)) - m0) * i0;
        t[1] = (lrelu(base + w2*(hist_s[1*64+p]/total)) - m1) * i1;
        t[2] = (lrelu(base + w2*(hist_s[2*64+p]/total)) - m2) * i2;
        t[3] = (lrelu(base + w2*(hist_s[3*64+p]/total)) - m3) * i3;
        float r[3][3] = {{0,0,0},{0,0,0},{0,0,0}};
        #pragma unroll
        for (int m = 0; m < 16; m++){
            float zm = lrelu(bc_s[m] + wc_s[m*4]*t[0] + wc_s[m*4+1]*t[1]
                                     + wc_s[m*4+2]*t[2] + wc_s[m*4+3]*t[3]);
            #pragma unroll
            for (int i = 0; i < 3; i++){
                r[i][0] += zm * wf_s[m*9 + i*3 + 0];
                r[i][1] += zm * wf_s[m*9 + i*3 + 1];
                r[i][2] += zm * wf_s[m*9 + i*3 + 2];
            }
        }
        int idx = b*64*168 + p*168 + oc*3;
        dR0[idx] = r[0][0]; dR0[idx+1] = r[0][1]; dR0[idx+2] = r[0][2];
        dR1[idx] = r[1][0]; dR1[idx+1] = r[1][1]; dR1[idx+2] = r[1][2];
        dR2[idx] = r[2][0]; dR2[idx+1] = r[2][1]; dR2[idx+2] = r[2][2];
    }
}

// ---- K4: final conv — tap tables from row-sums; vectorized output stores ----
__global__ void __launch_bounds__(256) k_final(const float* __restrict__ bf,
                                               float* __restrict__ out){
    __shared__ float u[3][168];
    __shared__ float obuf[3][256];
    int t = blockIdx.x, b = blockIdx.y;
    int tid = threadIdx.x;
    int rowbase = b*64*168 + t*168;

    for (int e = tid; e < 504; e += 256){
        int tbl = e / 168, k = e - tbl*168;
        float acc;
        if (tbl == 0){
            acc = dR1[rowbase + k] + dR2[rowbase + k];
            if (t > 0) acc += dR0[rowbase - 168 + k];
        } else if (tbl == 1){
            acc = dR0[rowbase + k] + dR1[rowbase + k] + dR2[rowbase + k];
        } else {
            acc = dR0[rowbase + k] + dR1[rowbase + k];
            if (t < 63) acc += dR2[rowbase + 168 + k];
        }
        u[tbl][k] = acc;
    }
    __syncthreads();

    {
        int w = tid;
        int gwC = (w*56) >> 8;
        int gwL = ((w-1)*56) >> 8;
        int gwR = ((w+1)*56) >> 8;
        float base = bf[0];
        #pragma unroll
        for (int tbl = 0; tbl < 3; tbl++){
            float acc = base + u[tbl][gwC*3 + 1];
            if (w > 0)   acc += u[tbl][gwL*3 + 0];
            if (w < 255) acc += u[tbl][gwR*3 + 2];
            obuf[tbl][w] = lrelu(acc);
        }
    }
    __syncthreads();

    // 4 output rows: srcs {0,1,1,2}
    {
        int r = tid >> 6, c4 = tid & 63;
        int src = (r == 0) ? 0 : (r == 3 ? 2 : 1);
        float4 v = ((float4*)obuf[src])[c4];
        *(float4*)&out[((size_t)b << 16) | ((size_t)(t*4+r) << 8) | (size_t)(c4*4)] = v;
    }
}

extern "C" void kernel_launch(void* const* d_in, const int* in_sizes, int n_in,
                              void* d_out, int out_size){
    const float* x    = (const float*)d_in[0];
    const float* we   = (const float*)d_in[1];
    const float* be   = (const float*)d_in[2];
    const float* wc   = (const float*)d_in[3];
    const float* bc   = (const float*)d_in[4];
    const float* wfin = (const float*)d_in[5];
    const float* bfin = (const float*)d_in[6];
    const float* clo  = (const float*)d_in[7];
    const float* chi  = (const float*)d_in[8];
    float* out = (float*)d_out;

    k_pool_minmax<<<dim3(8,16,16), dim3(32,8)>>>(x, clo, chi);
    k_hist       <<<dim3(8,16,16), 256>>>(clo, chi);
    k_grid       <<<128, 256>>>(we, be, wc, bc, wfin);
    k_final      <<<dim3(64,16), 256>>>(bfin, out);
}